// round 2
// baseline (speedup 1.0000x reference)
#include <cuda_runtime.h>
#include <math.h>

#define NN 100000
#define EE 1600000

// ---------------- scratch (device globals; no allocation) ----------------
__device__ float4 d_g1[NN * 16];    // (x@W1)*dinv   [N,64]
__device__ float4 d_agg1[NN * 16];  // edge-aggregated layer1
__device__ float4 d_h[NN * 16];     // relu output   [N,64]
__device__ float4 d_g2[NN * 10];    // (h@W2)*dinv   [N,40]
__device__ float4 d_agg2[NN * 10];  // edge-aggregated layer2
__device__ float  d_dinv[NN];
__device__ int    d_degc[NN];

// ---------------- zero scratch (must rerun every launch/replay) ----------
__global__ void k_zero() {
    int i = blockIdx.x * blockDim.x + threadIdx.x;
    float4 z = make_float4(0.f, 0.f, 0.f, 0.f);
    if (i < NN * 16) d_agg1[i] = z;
    if (i < NN * 10) d_agg2[i] = z;
    if (i < NN) d_degc[i] = 0;
}

// ---------------- degree over targets (col); self-loop added later ------
__global__ void k_count(const int* __restrict__ col) {
    int i = blockIdx.x * blockDim.x + threadIdx.x;
    if (i < EE) atomicAdd(&d_degc[__ldg(col + i)], 1);
}

__global__ void k_dinv() {
    int i = blockIdx.x * blockDim.x + threadIdx.x;
    if (i < NN) d_dinv[i] = rsqrtf((float)(d_degc[i] + 1));  // +1 self loop
}

// ---------------- GEMM1: g1 = (x @ W1) * dinv, tile 64 nodes x 64 outs ---
__global__ __launch_bounds__(256) void k_gemm1(const float4* __restrict__ x,
                                               const float* __restrict__ W) {
    __shared__ float ws[64 * 64];       // 16 KB
    __shared__ float xs[64 * 68];       // padded rows (68) vs bank conflicts
    int t = threadIdx.x;
    const float4* W4 = (const float4*)W;
#pragma unroll
    for (int i = 0; i < 4; i++) ((float4*)ws)[t + 256 * i] = __ldg(W4 + t + 256 * i);
    int node0 = blockIdx.x * 64;
#pragma unroll
    for (int i = 0; i < 4; i++) {
        int idx = t + 256 * i;          // 1024 float4 = 64 rows x 16
        int r = idx >> 4, c = idx & 15;
        int gr = node0 + r;
        float4 v = make_float4(0.f, 0.f, 0.f, 0.f);
        if (gr < NN) v = __ldg(x + gr * 16 + c);
        float* p = &xs[r * 68 + c * 4];
        p[0] = v.x; p[1] = v.y; p[2] = v.z; p[3] = v.w;
    }
    __syncthreads();
    int tx = t & 15, ty = t >> 4;       // tx: 16 groups of 4 outs; ty: 16 groups of 4 nodes
    float acc[4][4];
#pragma unroll
    for (int i = 0; i < 4; i++)
#pragma unroll
        for (int j = 0; j < 4; j++) acc[i][j] = 0.f;
#pragma unroll
    for (int k = 0; k < 64; k++) {
        float4 w = *(const float4*)&ws[k * 64 + tx * 4];
#pragma unroll
        for (int i = 0; i < 4; i++) {
            float xv = xs[(ty * 4 + i) * 68 + k];
            acc[i][0] += xv * w.x; acc[i][1] += xv * w.y;
            acc[i][2] += xv * w.z; acc[i][3] += xv * w.w;
        }
    }
#pragma unroll
    for (int i = 0; i < 4; i++) {
        int gr = node0 + ty * 4 + i;
        if (gr < NN) {
            float dv = d_dinv[gr];
            d_g1[gr * 16 + tx] = make_float4(acc[i][0] * dv, acc[i][1] * dv,
                                             acc[i][2] * dv, acc[i][3] * dv);
        }
    }
}

// ---------------- scatter1: agg1[col] += g1[row], 16 threads/edge --------
__global__ __launch_bounds__(256) void k_scatter1(const int* __restrict__ row,
                                                  const int* __restrict__ col) {
    int id = blockIdx.x * 256 + threadIdx.x;
    int e = id >> 4, lane = id & 15;
    if (e >= EE) return;
    int r = __ldg(row + e), c = __ldg(col + e);
    float4 v = __ldg((const float4*)d_g1 + r * 16 + lane);
    float* p = (float*)(d_agg1 + c * 16 + lane);
    asm volatile("red.global.add.v4.f32 [%0], {%1,%2,%3,%4};"
                 :: "l"(p), "f"(v.x), "f"(v.y), "f"(v.z), "f"(v.w) : "memory");
}

// ---------------- finish1: h = relu(dinv*(agg1+g1)+b1) -------------------
__global__ void k_finish1(const float* __restrict__ b1) {
    int i = blockIdx.x * blockDim.x + threadIdx.x;
    if (i >= NN * 16) return;
    int node = i >> 4, j4 = i & 15;
    float dv = d_dinv[node];
    float4 a = d_agg1[i], g = d_g1[i];
    float4 bb = __ldg((const float4*)b1 + j4);
    float4 h;
    h.x = fmaxf(dv * (a.x + g.x) + bb.x, 0.f);
    h.y = fmaxf(dv * (a.y + g.y) + bb.y, 0.f);
    h.z = fmaxf(dv * (a.z + g.z) + bb.z, 0.f);
    h.w = fmaxf(dv * (a.w + g.w) + bb.w, 0.f);
    d_h[i] = h;
}

// ---------------- GEMM2: g2 = (h @ W2) * dinv, tile 128 nodes x 40 outs --
__global__ __launch_bounds__(320) void k_gemm2(const float* __restrict__ W2) {
    __shared__ float ws[64 * 40];       // 10 KB
    __shared__ float xs[128 * 68];      // 34.8 KB
    int t = threadIdx.x;                // 320 threads
    for (int i = t; i < 640; i += 320)
        ((float4*)ws)[i] = __ldg((const float4*)W2 + i);
    int node0 = blockIdx.x * 128;
    for (int idx = t; idx < 2048; idx += 320) {   // 128 rows x 16 float4
        int r = idx >> 4, c = idx & 15;
        int gr = node0 + r;
        float4 v = make_float4(0.f, 0.f, 0.f, 0.f);
        if (gr < NN) v = d_h[gr * 16 + c];
        float* p = &xs[r * 68 + c * 4];
        p[0] = v.x; p[1] = v.y; p[2] = v.z; p[3] = v.w;
    }
    __syncthreads();
    int tx = t % 10, ty = t / 10;       // tx: 10 groups of 4 outs; ty: 32 groups of 4 nodes
    float acc[4][4];
#pragma unroll
    for (int i = 0; i < 4; i++)
#pragma unroll
        for (int j = 0; j < 4; j++) acc[i][j] = 0.f;
#pragma unroll
    for (int k = 0; k < 64; k++) {
        float4 w = *(const float4*)&ws[k * 40 + tx * 4];
#pragma unroll
        for (int i = 0; i < 4; i++) {
            float xv = xs[(ty * 4 + i) * 68 + k];
            acc[i][0] += xv * w.x; acc[i][1] += xv * w.y;
            acc[i][2] += xv * w.z; acc[i][3] += xv * w.w;
        }
    }
#pragma unroll
    for (int i = 0; i < 4; i++) {
        int gr = node0 + ty * 4 + i;
        if (gr < NN) {
            float dv = d_dinv[gr];
            d_g2[gr * 10 + tx] = make_float4(acc[i][0] * dv, acc[i][1] * dv,
                                             acc[i][2] * dv, acc[i][3] * dv);
        }
    }
}

// ---------------- scatter2: agg2[col] += g2[row], 10 threads/edge --------
__global__ __launch_bounds__(320) void k_scatter2(const int* __restrict__ row,
                                                  const int* __restrict__ col) {
    int t = threadIdx.x;
    int le = t / 10, j = t % 10;        // 32 edges per block
    int e = blockIdx.x * 32 + le;
    if (e >= EE) return;
    int r = __ldg(row + e), c = __ldg(col + e);
    float4 v = __ldg((const float4*)d_g2 + r * 10 + j);
    float* p = (float*)(d_agg2 + c * 10 + j);
    asm volatile("red.global.add.v4.f32 [%0], {%1,%2,%3,%4};"
                 :: "l"(p), "f"(v.x), "f"(v.y), "f"(v.z), "f"(v.w) : "memory");
}

// ---------------- finish2 + log_softmax: one warp per node ---------------
__global__ void k_softmax(const float* __restrict__ b2, float* __restrict__ out) {
    int gw = (blockIdx.x * blockDim.x + threadIdx.x) >> 5;
    int lane = threadIdx.x & 31;
    if (gw >= NN) return;
    float dv = d_dinv[gw];
    const float* ap = (const float*)d_agg2 + gw * 40;
    const float* gp = (const float*)d_g2 + gw * 40;
    float z0 = dv * (ap[lane] + gp[lane]) + __ldg(b2 + lane);
    float z1 = (lane < 8) ? dv * (ap[32 + lane] + gp[32 + lane]) + __ldg(b2 + 32 + lane)
                          : -INFINITY;
    float m = fmaxf(z0, z1);
#pragma unroll
    for (int o = 16; o; o >>= 1) m = fmaxf(m, __shfl_xor_sync(0xFFFFFFFFu, m, o));
    float s = expf(z0 - m) + ((lane < 8) ? expf(z1 - m) : 0.f);
#pragma unroll
    for (int o = 16; o; o >>= 1) s += __shfl_xor_sync(0xFFFFFFFFu, s, o);
    float lse = m + logf(s);
    out[gw * 40 + lane] = z0 - lse;
    if (lane < 8) out[gw * 40 + 32 + lane] = z1 - lse;
}

// ---------------- launch --------------------------------------------------
extern "C" void kernel_launch(void* const* d_in, const int* in_sizes, int n_in,
                              void* d_out, int out_size) {
    const float* x  = (const float*)d_in[0];
    const int*   ei = (const int*)d_in[1];
    const float* W1 = (const float*)d_in[2];
    const float* b1 = (const float*)d_in[3];
    const float* W2 = (const float*)d_in[4];
    const float* b2 = (const float*)d_in[5];
    const int* row = ei;        // edge_index[0] = sources (gathered)
    const int* col = ei + EE;   // edge_index[1] = targets (scatter-add)
    float* out = (float*)d_out;

    k_zero<<<(NN * 16 + 255) / 256, 256>>>();
    k_count<<<(EE + 255) / 256, 256>>>(col);
    k_dinv<<<(NN + 255) / 256, 256>>>();
    k_gemm1<<<(NN + 63) / 64, 256>>>((const float4*)x, W1);
    k_scatter1<<<(EE * 16 + 255) / 256, 256>>>(row, col);
    k_finish1<<<(NN * 16 + 255) / 256, 256>>>(b1);
    k_gemm2<<<(NN + 127) / 128, 320>>>(W2);
    k_scatter2<<<(EE + 31) / 32, 320>>>(row, col);
    k_softmax<<<(NN * 32 + 255) / 256, 256>>>(b2, out);
}

// round 4
// speedup vs baseline: 1.4364x; 1.4364x over previous
#include <cuda_runtime.h>
#include <math.h>

#define NN 100000
#define EE 1600000
#define NB 196          // ceil(NN/512) scan blocks

// ---------------- scratch (device globals; no allocation) ----------------
__device__ float4 d_g1[NN * 16];    // (x@W1)*dinv   [N,64]
__device__ float4 d_h[NN * 16];     // relu output   [N,64]
__device__ float4 d_g2[NN * 10];    // (h@W2)*dinv   [N,40]
__device__ float  d_dinv[NN];
__device__ int    d_degc[NN];
__device__ int    d_start[NN];
__device__ int    d_cursor[NN];
__device__ int    d_adj[EE];
__device__ int    d_part[256];

// ---------------- zero degree counters -----------------------------------
__global__ void k_zero_deg() {
    int i = blockIdx.x * blockDim.x + threadIdx.x;
    if (i < NN) d_degc[i] = 0;
}

// ---------------- degree over targets (col) ------------------------------
__global__ void k_count(const int* __restrict__ col) {
    int i = blockIdx.x * blockDim.x + threadIdx.x;
    if (i < EE) atomicAdd(&d_degc[__ldg(col + i)], 1);
}

// ---------------- scan phase 1: per-block exclusive scan of degc ---------
__global__ __launch_bounds__(512) void k_scan1() {
    __shared__ int sh[512];
    int t = threadIdx.x;
    int i = blockIdx.x * 512 + t;
    int v = (i < NN) ? d_degc[i] : 0;
    sh[t] = v;
    __syncthreads();
#pragma unroll
    for (int off = 1; off < 512; off <<= 1) {
        int a = (t >= off) ? sh[t - off] : 0;
        __syncthreads();
        sh[t] += a;
        __syncthreads();
    }
    if (i < NN) d_start[i] = sh[t] - v;           // exclusive, block-local
    if (t == 511) d_part[blockIdx.x] = sh[t];     // block total
}

// ---------------- scan phase 2: scan the 196 block totals ----------------
__global__ __launch_bounds__(256) void k_scan2() {
    __shared__ int sh[256];
    int t = threadIdx.x;
    int v = (t < NB) ? d_part[t] : 0;
    sh[t] = v;
    __syncthreads();
#pragma unroll
    for (int off = 1; off < 256; off <<= 1) {
        int a = (t >= off) ? sh[t - off] : 0;
        __syncthreads();
        sh[t] += a;
        __syncthreads();
    }
    if (t < NB) d_part[t] = sh[t] - v;            // exclusive
}

// ---------------- scan phase 3: finalize offsets, cursor, dinv -----------
__global__ void k_scan3() {
    int i = blockIdx.x * blockDim.x + threadIdx.x;
    if (i >= NN) return;
    int s = d_start[i] + d_part[i >> 9];
    d_start[i] = s;
    d_cursor[i] = s;
    d_dinv[i] = rsqrtf((float)(d_degc[i] + 1));   // +1 self loop
}

// ---------------- fill adjacency: adj[cursor[c]++] = row -----------------
__global__ void k_fill(const int* __restrict__ row, const int* __restrict__ col) {
    int e = blockIdx.x * blockDim.x + threadIdx.x;
    if (e >= EE) return;
    int c = __ldg(col + e);
    int p = atomicAdd(&d_cursor[c], 1);
    d_adj[p] = __ldg(row + e);
}

// ---------------- GEMM1: g1 = (x @ W1) * dinv, tile 64 nodes x 64 outs ---
__global__ __launch_bounds__(256) void k_gemm1(const float4* __restrict__ x,
                                               const float* __restrict__ W) {
    __shared__ float ws[64 * 64];
    __shared__ float xs[64 * 68];
    int t = threadIdx.x;
    const float4* W4 = (const float4*)W;
#pragma unroll
    for (int i = 0; i < 4; i++) ((float4*)ws)[t + 256 * i] = __ldg(W4 + t + 256 * i);
    int node0 = blockIdx.x * 64;
#pragma unroll
    for (int i = 0; i < 4; i++) {
        int idx = t + 256 * i;
        int r = idx >> 4, c = idx & 15;
        int gr = node0 + r;
        float4 v = make_float4(0.f, 0.f, 0.f, 0.f);
        if (gr < NN) v = __ldg(x + gr * 16 + c);
        float* p = &xs[r * 68 + c * 4];
        p[0] = v.x; p[1] = v.y; p[2] = v.z; p[3] = v.w;
    }
    __syncthreads();
    int tx = t & 15, ty = t >> 4;
    float acc[4][4];
#pragma unroll
    for (int i = 0; i < 4; i++)
#pragma unroll
        for (int j = 0; j < 4; j++) acc[i][j] = 0.f;
#pragma unroll
    for (int k = 0; k < 64; k++) {
        float4 w = *(const float4*)&ws[k * 64 + tx * 4];
#pragma unroll
        for (int i = 0; i < 4; i++) {
            float xv = xs[(ty * 4 + i) * 68 + k];
            acc[i][0] += xv * w.x; acc[i][1] += xv * w.y;
            acc[i][2] += xv * w.z; acc[i][3] += xv * w.w;
        }
    }
#pragma unroll
    for (int i = 0; i < 4; i++) {
        int gr = node0 + ty * 4 + i;
        if (gr < NN) {
            float dv = d_dinv[gr];
            d_g1[gr * 16 + tx] = make_float4(acc[i][0] * dv, acc[i][1] * dv,
                                             acc[i][2] * dv, acc[i][3] * dv);
        }
    }
}

// ---------------- agg1 (gather) + finish1: one warp per node -------------
// lanes 0-15 handle even edges, 16-31 odd edges; each lane owns one float4
// feature chunk. h = relu(dinv*(sum + g1_self) + b1)
__global__ __launch_bounds__(256) void k_agg1(const float* __restrict__ b1) {
    int w = (blockIdx.x * blockDim.x + threadIdx.x) >> 5;
    if (w >= NN) return;
    int lane = threadIdx.x & 31;
    int half = lane >> 4, fl = lane & 15;
    int s = d_start[w], d = d_degc[w];
    float4 acc = make_float4(0.f, 0.f, 0.f, 0.f);
#pragma unroll 4
    for (int i = half; i < d; i += 2) {
        int r = __ldg(d_adj + s + i);
        float4 v = __ldg((const float4*)d_g1 + r * 16 + fl);
        acc.x += v.x; acc.y += v.y; acc.z += v.z; acc.w += v.w;
    }
    acc.x += __shfl_xor_sync(0xFFFFFFFFu, acc.x, 16);
    acc.y += __shfl_xor_sync(0xFFFFFFFFu, acc.y, 16);
    acc.z += __shfl_xor_sync(0xFFFFFFFFu, acc.z, 16);
    acc.w += __shfl_xor_sync(0xFFFFFFFFu, acc.w, 16);
    if (half == 0) {
        float dv = d_dinv[w];
        float4 g = d_g1[w * 16 + fl];
        float4 bb = __ldg((const float4*)b1 + fl);
        float4 h;
        h.x = fmaxf(dv * (acc.x + g.x) + bb.x, 0.f);
        h.y = fmaxf(dv * (acc.y + g.y) + bb.y, 0.f);
        h.z = fmaxf(dv * (acc.z + g.z) + bb.z, 0.f);
        h.w = fmaxf(dv * (acc.w + g.w) + bb.w, 0.f);
        d_h[w * 16 + fl] = h;
    }
}

// ---------------- GEMM2: g2 = (h @ W2) * dinv ----------------------------
__global__ __launch_bounds__(320) void k_gemm2(const float* __restrict__ W2) {
    __shared__ float ws[64 * 40];
    __shared__ float xs[128 * 68];
    int t = threadIdx.x;
    for (int i = t; i < 640; i += 320)
        ((float4*)ws)[i] = __ldg((const float4*)W2 + i);
    int node0 = blockIdx.x * 128;
    for (int idx = t; idx < 2048; idx += 320) {
        int r = idx >> 4, c = idx & 15;
        int gr = node0 + r;
        float4 v = make_float4(0.f, 0.f, 0.f, 0.f);
        if (gr < NN) v = d_h[gr * 16 + c];
        float* p = &xs[r * 68 + c * 4];
        p[0] = v.x; p[1] = v.y; p[2] = v.z; p[3] = v.w;
    }
    __syncthreads();
    int tx = t % 10, ty = t / 10;
    float acc[4][4];
#pragma unroll
    for (int i = 0; i < 4; i++)
#pragma unroll
        for (int j = 0; j < 4; j++) acc[i][j] = 0.f;
#pragma unroll
    for (int k = 0; k < 64; k++) {
        float4 w = *(const float4*)&ws[k * 40 + tx * 4];
#pragma unroll
        for (int i = 0; i < 4; i++) {
            float xv = xs[(ty * 4 + i) * 68 + k];
            acc[i][0] += xv * w.x; acc[i][1] += xv * w.y;
            acc[i][2] += xv * w.z; acc[i][3] += xv * w.w;
        }
    }
#pragma unroll
    for (int i = 0; i < 4; i++) {
        int gr = node0 + ty * 4 + i;
        if (gr < NN) {
            float dv = d_dinv[gr];
            d_g2[gr * 10 + tx] = make_float4(acc[i][0] * dv, acc[i][1] * dv,
                                             acc[i][2] * dv, acc[i][3] * dv);
        }
    }
}

// ---------------- agg2 (gather) + bias + log_softmax: one warp per node --
// 10 feature float4-chunks; 3 edge groups of 10 lanes (lanes 30,31 idle).
__global__ __launch_bounds__(256) void k_agg2(const float* __restrict__ b2,
                                              float* __restrict__ out) {
    int w = (blockIdx.x * blockDim.x + threadIdx.x) >> 5;
    if (w >= NN) return;
    int lane = threadIdx.x & 31;
    int grp = lane / 10, fl = lane % 10;
    int s = d_start[w], d = d_degc[w];
    float4 acc = make_float4(0.f, 0.f, 0.f, 0.f);
    if (grp < 3) {
#pragma unroll 4
        for (int i = grp; i < d; i += 3) {
            int r = __ldg(d_adj + s + i);
            float4 v = __ldg((const float4*)d_g2 + r * 10 + fl);
            acc.x += v.x; acc.y += v.y; acc.z += v.z; acc.w += v.w;
        }
    }
    // combine the 3 edge groups: lane l (<10) sums lanes l, l+10, l+20
    float4 o1, o2;
    o1.x = __shfl_sync(0xFFFFFFFFu, acc.x, lane + 10);
    o1.y = __shfl_sync(0xFFFFFFFFu, acc.y, lane + 10);
    o1.z = __shfl_sync(0xFFFFFFFFu, acc.z, lane + 10);
    o1.w = __shfl_sync(0xFFFFFFFFu, acc.w, lane + 10);
    o2.x = __shfl_sync(0xFFFFFFFFu, acc.x, lane + 20);
    o2.y = __shfl_sync(0xFFFFFFFFu, acc.y, lane + 20);
    o2.z = __shfl_sync(0xFFFFFFFFu, acc.z, lane + 20);
    o2.w = __shfl_sync(0xFFFFFFFFu, acc.w, lane + 20);
    acc.x += o1.x + o2.x; acc.y += o1.y + o2.y;
    acc.z += o1.z + o2.z; acc.w += o1.w + o2.w;

    float4 z = make_float4(-INFINITY, -INFINITY, -INFINITY, -INFINITY);
    if (lane < 10) {
        float dv = d_dinv[w];
        float4 g = d_g2[w * 10 + lane];
        float4 bb = __ldg((const float4*)b2 + lane);
        z.x = dv * (acc.x + g.x) + bb.x;
        z.y = dv * (acc.y + g.y) + bb.y;
        z.z = dv * (acc.z + g.z) + bb.z;
        z.w = dv * (acc.w + g.w) + bb.w;
    }
    // max over 40 values: per-lane max4, then xor-reduce within lanes 0-15
    float m = fmaxf(fmaxf(z.x, z.y), fmaxf(z.z, z.w));   // -INF on lanes>=10
#pragma unroll
    for (int o = 8; o; o >>= 1) m = fmaxf(m, __shfl_xor_sync(0xFFFFFFFFu, m, o));
    float sm = 0.f;
    if (lane < 10)
        sm = expf(z.x - m) + expf(z.y - m) + expf(z.z - m) + expf(z.w - m);
#pragma unroll
    for (int o = 8; o; o >>= 1) sm += __shfl_xor_sync(0xFFFFFFFFu, sm, o);
    if (lane < 10) {
        float lse = m + logf(sm);
        float4 r = make_float4(z.x - lse, z.y - lse, z.z - lse, z.w - lse);
        ((float4*)out)[w * 10 + lane] = r;
    }
}

// ---------------- launch --------------------------------------------------
extern "C" void kernel_launch(void* const* d_in, const int* in_sizes, int n_in,
                              void* d_out, int out_size) {
    const float* x  = (const float*)d_in[0];
    const int*   ei = (const int*)d_in[1];
    const float* W1 = (const float*)d_in[2];
    const float* b1 = (const float*)d_in[3];
    const float* W2 = (const float*)d_in[4];
    const float* b2 = (const float*)d_in[5];
    const int* row = ei;        // edge_index[0] = sources (gathered)
    const int* col = ei + EE;   // edge_index[1] = targets (aggregated)
    float* out = (float*)d_out;

    k_zero_deg<<<(NN + 255) / 256, 256>>>();
    k_count<<<(EE + 255) / 256, 256>>>(col);
    k_scan1<<<NB, 512>>>();
    k_scan2<<<1, 256>>>();
    k_scan3<<<(NN + 255) / 256, 256>>>();
    k_fill<<<(EE + 255) / 256, 256>>>(row, col);
    k_gemm1<<<(NN + 63) / 64, 256>>>((const float4*)x, W1);
    k_agg1<<<(NN * 32 + 255) / 256, 256>>>(b1);
    k_gemm2<<<(NN + 127) / 128, 320>>>(W2);
    k_agg2<<<(NN * 32 + 255) / 256, 256>>>(b2, out);
}

// round 8
// speedup vs baseline: 1.5684x; 1.0919x over previous
#include <cuda_runtime.h>
#include <cuda_fp16.h>
#include <math.h>

#define NN 100000
#define EE 1600000
#define NSCAN 196            // ceil(NN/512)
#define G1BLK 1563           // ceil(NN/64) gemm1 blocks
#define FILLBLK 6250         // ceil(EE/256) fill blocks

// ---------------- scratch (device globals; no allocation) ----------------
__device__ __half  d_g1h[NN * 64];   // (x@W1)*dinv  fp16  [N,64]  128B rows
__device__ float4  d_h[NN * 16];     // relu output  fp32  [N,64]
__device__ __half  d_g2h[NN * 64];   // (h@W2)*dinv  fp16  [N,40] padded to 64
__device__ float   d_dinv[NN];
__device__ int     d_degc[NN];
__device__ int     d_start[NN];
__device__ int     d_cursor[NN];
__device__ int     d_adj[EE];
__device__ int     d_gbase;

// ---------------- zero counters ------------------------------------------
__global__ void k_zero() {
    int i = blockIdx.x * blockDim.x + threadIdx.x;
    if (i < NN) d_degc[i] = 0;
    if (i == 0) d_gbase = 0;
}

// ---------------- degree over targets (col) ------------------------------
__global__ void k_count(const int* __restrict__ col) {
    int i = blockIdx.x * blockDim.x + threadIdx.x;
    if (i < EE) atomicAdd(&d_degc[__ldg(col + i)], 1);
}

// ---------------- single-kernel scan: block scan + atomic base -----------
__global__ __launch_bounds__(512) void k_scan() {
    __shared__ int sh[512];
    __shared__ int base;
    int t = threadIdx.x;
    int i = blockIdx.x * 512 + t;
    int v = (i < NN) ? d_degc[i] : 0;
    sh[t] = v;
    __syncthreads();
#pragma unroll
    for (int off = 1; off < 512; off <<= 1) {
        int a = (t >= off) ? sh[t - off] : 0;
        __syncthreads();
        sh[t] += a;
        __syncthreads();
    }
    if (t == 511) base = atomicAdd(&d_gbase, sh[511]);
    __syncthreads();
    if (i < NN) {
        int s = base + sh[t] - v;      // exclusive prefix within block + base
        d_start[i] = s;
        d_cursor[i] = s;
        d_dinv[i] = rsqrtf((float)(v + 1));   // +1 self loop
    }
}

// ---------------- fused: CSR fill (atomic-bound)  ||  GEMM1 (fma-bound) --
// blocks [0, G1BLK): g1 = (x @ W1) * dinv  -> fp16
// blocks [G1BLK, G1BLK+FILLBLK): adj[cursor[c]++] = row
__global__ __launch_bounds__(256) void k_fill_gemm1(const int* __restrict__ row,
                                                    const int* __restrict__ col,
                                                    const float4* __restrict__ x,
                                                    const float* __restrict__ W) {
    __shared__ float ws[64 * 64];
    __shared__ float xs[64 * 68];
    if (blockIdx.x >= G1BLK) {
        int e = (blockIdx.x - G1BLK) * 256 + threadIdx.x;
        if (e < EE) {
            int c = __ldg(col + e);
            int p = atomicAdd(&d_cursor[c], 1);
            d_adj[p] = __ldg(row + e);
        }
        return;
    }
    int t = threadIdx.x;
    const float4* W4 = (const float4*)W;
#pragma unroll
    for (int i = 0; i < 4; i++) ((float4*)ws)[t + 256 * i] = __ldg(W4 + t + 256 * i);
    int node0 = blockIdx.x * 64;
#pragma unroll
    for (int i = 0; i < 4; i++) {
        int idx = t + 256 * i;
        int r = idx >> 4, c = idx & 15;
        int gr = node0 + r;
        float4 v = make_float4(0.f, 0.f, 0.f, 0.f);
        if (gr < NN) v = __ldg(x + gr * 16 + c);
        float* p = &xs[r * 68 + c * 4];
        p[0] = v.x; p[1] = v.y; p[2] = v.z; p[3] = v.w;
    }
    __syncthreads();
    int tx = t & 15, ty = t >> 4;
    float acc[4][4];
#pragma unroll
    for (int i = 0; i < 4; i++)
#pragma unroll
        for (int j = 0; j < 4; j++) acc[i][j] = 0.f;
#pragma unroll
    for (int k = 0; k < 64; k++) {
        float4 w = *(const float4*)&ws[k * 64 + tx * 4];
#pragma unroll
        for (int i = 0; i < 4; i++) {
            float xv = xs[(ty * 4 + i) * 68 + k];
            acc[i][0] += xv * w.x; acc[i][1] += xv * w.y;
            acc[i][2] += xv * w.z; acc[i][3] += xv * w.w;
        }
    }
#pragma unroll
    for (int i = 0; i < 4; i++) {
        int gr = node0 + ty * 4 + i;
        if (gr < NN) {
            float dv = d_dinv[gr];
            __half2 a = __float22half2_rn(make_float2(acc[i][0] * dv, acc[i][1] * dv));
            __half2 b = __float22half2_rn(make_float2(acc[i][2] * dv, acc[i][3] * dv));
            ((__half2*)d_g1h)[gr * 32 + tx * 2] = a;
            ((__half2*)d_g1h)[gr * 32 + tx * 2 + 1] = b;
        }
    }
}

// ---------------- agg1 (fp16 gather) + relu/bias: one warp per node ------
// 4 edge groups x 8 lanes; each lane owns 8 features (uint4 = 8 halves).
__global__ __launch_bounds__(256) void k_agg1(const float* __restrict__ b1) {
    int w = (blockIdx.x * blockDim.x + threadIdx.x) >> 5;
    if (w >= NN) return;
    int lane = threadIdx.x & 31;
    int grp = lane >> 3, fl = lane & 7;
    int s = d_start[w], d = d_degc[w];
    const uint4* G = (const uint4*)d_g1h;
    float acc[8];
#pragma unroll
    for (int j = 0; j < 8; j++) acc[j] = 0.f;
#pragma unroll 2
    for (int i = grp; i < d; i += 4) {
        int r = __ldg(d_adj + s + i);
        uint4 u = __ldg(G + r * 8 + fl);
        const __half2* hp = (const __half2*)&u;
        float2 f;
        f = __half22float2(hp[0]); acc[0] += f.x; acc[1] += f.y;
        f = __half22float2(hp[1]); acc[2] += f.x; acc[3] += f.y;
        f = __half22float2(hp[2]); acc[4] += f.x; acc[5] += f.y;
        f = __half22float2(hp[3]); acc[6] += f.x; acc[7] += f.y;
    }
#pragma unroll
    for (int j = 0; j < 8; j++) {
        acc[j] += __shfl_xor_sync(0xFFFFFFFFu, acc[j], 8);
        acc[j] += __shfl_xor_sync(0xFFFFFFFFu, acc[j], 16);
    }
    if (grp == 0) {
        float dv = d_dinv[w];
        uint4 us = __ldg(G + w * 8 + fl);          // self message
        const __half2* hs = (const __half2*)&us;
        float gs[8];
        float2 f;
        f = __half22float2(hs[0]); gs[0] = f.x; gs[1] = f.y;
        f = __half22float2(hs[1]); gs[2] = f.x; gs[3] = f.y;
        f = __half22float2(hs[2]); gs[4] = f.x; gs[5] = f.y;
        f = __half22float2(hs[3]); gs[6] = f.x; gs[7] = f.y;
        float4 ba = __ldg((const float4*)b1 + fl * 2);
        float4 bb = __ldg((const float4*)b1 + fl * 2 + 1);
        float4 h0, h1;
        h0.x = fmaxf(dv * (acc[0] + gs[0]) + ba.x, 0.f);
        h0.y = fmaxf(dv * (acc[1] + gs[1]) + ba.y, 0.f);
        h0.z = fmaxf(dv * (acc[2] + gs[2]) + ba.z, 0.f);
        h0.w = fmaxf(dv * (acc[3] + gs[3]) + ba.w, 0.f);
        h1.x = fmaxf(dv * (acc[4] + gs[4]) + bb.x, 0.f);
        h1.y = fmaxf(dv * (acc[5] + gs[5]) + bb.y, 0.f);
        h1.z = fmaxf(dv * (acc[6] + gs[6]) + bb.z, 0.f);
        h1.w = fmaxf(dv * (acc[7] + gs[7]) + bb.w, 0.f);
        d_h[w * 16 + fl * 2] = h0;
        d_h[w * 16 + fl * 2 + 1] = h1;
    }
}

// ---------------- GEMM2: g2 = (h @ W2) * dinv -> fp16 (padded rows) ------
__global__ __launch_bounds__(320) void k_gemm2(const float* __restrict__ W2) {
    __shared__ float ws[64 * 40];
    __shared__ float xs[128 * 68];
    int t = threadIdx.x;
    for (int i = t; i < 640; i += 320)
        ((float4*)ws)[i] = __ldg((const float4*)W2 + i);
    int node0 = blockIdx.x * 128;
    for (int idx = t; idx < 2048; idx += 320) {
        int r = idx >> 4, c = idx & 15;
        int gr = node0 + r;
        float4 v = make_float4(0.f, 0.f, 0.f, 0.f);
        if (gr < NN) v = d_h[gr * 16 + c];
        float* p = &xs[r * 68 + c * 4];
        p[0] = v.x; p[1] = v.y; p[2] = v.z; p[3] = v.w;
    }
    __syncthreads();
    int tx = t % 10, ty = t / 10;
    float acc[4][4];
#pragma unroll
    for (int i = 0; i < 4; i++)
#pragma unroll
        for (int j = 0; j < 4; j++) acc[i][j] = 0.f;
#pragma unroll
    for (int k = 0; k < 64; k++) {
        float4 w = *(const float4*)&ws[k * 40 + tx * 4];
#pragma unroll
        for (int i = 0; i < 4; i++) {
            float xv = xs[(ty * 4 + i) * 68 + k];
            acc[i][0] += xv * w.x; acc[i][1] += xv * w.y;
            acc[i][2] += xv * w.z; acc[i][3] += xv * w.w;
        }
    }
#pragma unroll
    for (int i = 0; i < 4; i++) {
        int gr = node0 + ty * 4 + i;
        if (gr < NN) {
            float dv = d_dinv[gr];
            __half2 a = __float22half2_rn(make_float2(acc[i][0] * dv, acc[i][1] * dv));
            __half2 b = __float22half2_rn(make_float2(acc[i][2] * dv, acc[i][3] * dv));
            ((__half2*)d_g2h)[gr * 32 + tx * 2] = a;
            ((__half2*)d_g2h)[gr * 32 + tx * 2 + 1] = b;
        }
    }
}

// ---------------- agg2 (fp16 gather) + bias + log_softmax ----------------
// 3 edge groups x 10 lanes; each lane owns 4 features (uint2 = 4 halves).
__global__ __launch_bounds__(256) void k_agg2(const float* __restrict__ b2,
                                              float* __restrict__ out) {
    int w = (blockIdx.x * blockDim.x + threadIdx.x) >> 5;
    if (w >= NN) return;
    int lane = threadIdx.x & 31;
    int grp = lane / 10, fl = lane % 10;
    int s = d_start[w], d = d_degc[w];
    const uint2* G = (const uint2*)d_g2h;      // 16 uint2 per padded row
    float a0 = 0.f, a1 = 0.f, a2 = 0.f, a3 = 0.f;
    if (grp < 3) {
#pragma unroll 2
        for (int i = grp; i < d; i += 3) {
            int r = __ldg(d_adj + s + i);
            uint2 u = __ldg(G + r * 16 + fl);
            const __half2* hp = (const __half2*)&u;
            float2 f0 = __half22float2(hp[0]), f1 = __half22float2(hp[1]);
            a0 += f0.x; a1 += f0.y; a2 += f1.x; a3 += f1.y;
        }
    }
    // combine the 3 edge groups: lane l (<10) sums lanes l, l+10, l+20
    a0 += __shfl_sync(0xFFFFFFFFu, a0, lane + 10) + __shfl_sync(0xFFFFFFFFu, a0, lane + 20);
    a1 += __shfl_sync(0xFFFFFFFFu, a1, lane + 10) + __shfl_sync(0xFFFFFFFFu, a1, lane + 20);
    a2 += __shfl_sync(0xFFFFFFFFu, a2, lane + 10) + __shfl_sync(0xFFFFFFFFu, a2, lane + 20);
    a3 += __shfl_sync(0xFFFFFFFFu, a3, lane + 10) + __shfl_sync(0xFFFFFFFFu, a3, lane + 20);

    float4 z = make_float4(-INFINITY, -INFINITY, -INFINITY, -INFINITY);
    if (lane < 10) {
        float dv = d_dinv[w];
        uint2 us = __ldg(G + w * 16 + lane);       // self message
        const __half2* hs = (const __half2*)&us;
        float2 g0 = __half22float2(hs[0]), g1 = __half22float2(hs[1]);
        float4 bb = __ldg((const float4*)b2 + lane);
        z.x = dv * (a0 + g0.x) + bb.x;
        z.y = dv * (a1 + g0.y) + bb.y;
        z.z = dv * (a2 + g1.x) + bb.z;
        z.w = dv * (a3 + g1.y) + bb.w;
    }
    float m = fmaxf(fmaxf(z.x, z.y), fmaxf(z.z, z.w));
#pragma unroll
    for (int o = 8; o; o >>= 1) m = fmaxf(m, __shfl_xor_sync(0xFFFFFFFFu, m, o));
    float sm = 0.f;
    if (lane < 10)
        sm = expf(z.x - m) + expf(z.y - m) + expf(z.z - m) + expf(z.w - m);
#pragma unroll
    for (int o = 8; o; o >>= 1) sm += __shfl_xor_sync(0xFFFFFFFFu, sm, o);
    if (lane < 10) {
        float lse = m + logf(sm);
        ((float4*)out)[w * 10 + lane] =
            make_float4(z.x - lse, z.y - lse, z.z - lse, z.w - lse);
    }
}

// ---------------- launch --------------------------------------------------
extern "C" void kernel_launch(void* const* d_in, const int* in_sizes, int n_in,
                              void* d_out, int out_size) {
    const float* x  = (const float*)d_in[0];
    const int*   ei = (const int*)d_in[1];
    const float* W1 = (const float*)d_in[2];
    const float* b1 = (const float*)d_in[3];
    const float* W2 = (const float*)d_in[4];
    const float* b2 = (const float*)d_in[5];
    const int* row = ei;        // edge_index[0] = sources (gathered)
    const int* col = ei + EE;   // edge_index[1] = targets (aggregated)
    float* out = (float*)d_out;

    k_zero<<<(NN + 255) / 256, 256>>>();
    k_count<<<(EE + 255) / 256, 256>>>(col);
    k_scan<<<NSCAN, 512>>>();
    k_fill_gemm1<<<G1BLK + FILLBLK, 256>>>(row, col, (const float4*)x, W1);
    k_agg1<<<(NN * 32 + 255) / 256, 256>>>(b1);
    k_gemm2<<<(NN + 127) / 128, 320>>>(W2);
    k_agg2<<<(NN * 32 + 255) / 256, 256>>>(b2, out);
}